// round 5
// baseline (speedup 1.0000x reference)
#include <cuda_runtime.h>
#include <cstdint>

#define DMODEL 512
#define NHEAD  8
#define DK     64
#define BATCH  2
#define SEQ    4096
#define MTOT   (BATCH*SEQ)   // 8192

// Scratch (static device arrays — no runtime allocation)
// All tf32 operand buffers use k-axis permutation within 16-element blocks:
//   stored position of logical k:  (k & ~15) + 4*(k&3) + ((k&15)>>2)
__device__ float g_qh[(size_t)BATCH*NHEAD*SEQ*DK];   // [B,H,S,Dk] d-permuted, *1/8
__device__ float g_kh[(size_t)BATCH*NHEAD*SEQ*DK];   // [B,H,S,Dk] d-permuted
__device__ float g_vh[(size_t)BATCH*NHEAD*SEQ*DK];   // [B,H,Dk,S] key-permuted
__device__ float g_att[(size_t)MTOT*DMODEL];         // [B,S,D] D-permuted
__device__ float g_rq[(size_t)MTOT*DMODEL];          // rounded+permuted inputs
__device__ float g_rk[(size_t)MTOT*DMODEL];
__device__ float g_rv[(size_t)MTOT*DMODEL];
__device__ float g_rw[(size_t)4*DMODEL*DMODEL];      // rounded+permuted weights

// ---------------------------------------------------------------------------
__device__ __forceinline__ uint32_t f2tf(float f) {
    uint32_t u;
    asm("cvt.rna.tf32.f32 %0, %1;" : "=r"(u) : "f"(f));
    return u;
}
__device__ __forceinline__ float rnaf(float f) { return __uint_as_float(f2tf(f)); }

__device__ __forceinline__ void mma_tf32(float* d, uint32_t a0, uint32_t a1,
                                         uint32_t a2, uint32_t a3,
                                         uint32_t b0, uint32_t b1) {
    asm volatile(
        "mma.sync.aligned.m16n8k8.row.col.f32.tf32.tf32.f32 "
        "{%0,%1,%2,%3}, {%4,%5,%6,%7}, {%8,%9}, {%0,%1,%2,%3};\n"
        : "+f"(d[0]), "+f"(d[1]), "+f"(d[2]), "+f"(d[3])
        : "r"(a0), "r"(a1), "r"(a2), "r"(a3), "r"(b0), "r"(b1));
}
#define U(x) __float_as_uint(x)

__device__ __forceinline__ void cp16(uint32_t saddr, const void* g) {
    asm volatile("cp.async.cg.shared.global [%0], [%1], 16;\n"
                 :: "r"(saddr), "l"(g));
}
__device__ __forceinline__ void cpcommit() {
    asm volatile("cp.async.commit_group;\n");
}
template<int N> __device__ __forceinline__ void cpwait() {
    asm volatile("cp.async.wait_group %0;\n" :: "n"(N));
}

// ---------------------------------------------------------------------------
// Batched rna-round + k-permute (within 16-blocks) to feed tf32 mma fragments.
// dst[(k&~15) + ((k&15)>>2) + 4*(k&3)] = rnaf(src[k]); float4 src -> stride-4.
// ---------------------------------------------------------------------------
__device__ __forceinline__ void round_perm_one(const float4* __restrict__ s,
                                               float* __restrict__ d, int n4)
{
    for (int i = blockIdx.x * blockDim.x + threadIdx.x; i < n4;
         i += gridDim.x * blockDim.x) {
        float4 v = s[i];
        int k0 = 4 * i;
        int base = (k0 & ~15) + ((k0 & 15) >> 2);
        d[base + 0]  = rnaf(v.x);
        d[base + 4]  = rnaf(v.y);
        d[base + 8]  = rnaf(v.z);
        d[base + 12] = rnaf(v.w);
    }
}

__global__ void round3_kernel(const float4* __restrict__ s0,
                              const float4* __restrict__ s1,
                              const float4* __restrict__ s2,
                              float* __restrict__ d0,
                              float* __restrict__ d1,
                              float* __restrict__ d2, int n4)
{
    const float4* s = (blockIdx.y == 0) ? s0 : (blockIdx.y == 1) ? s1 : s2;
    float*        d = (blockIdx.y == 0) ? d0 : (blockIdx.y == 1) ? d1 : d2;
    round_perm_one(s, d, n4);
}

__global__ void round4_kernel(const float4* __restrict__ s0,
                              const float4* __restrict__ s1,
                              const float4* __restrict__ s2,
                              const float4* __restrict__ s3,
                              float* __restrict__ dst, int n4)
{
    const float4* s = (blockIdx.y == 0) ? s0 : (blockIdx.y == 1) ? s1
                    : (blockIdx.y == 2) ? s2 : s3;
    round_perm_one(s, dst + (size_t)blockIdx.y * n4 * 4, n4);
}

// ---------------------------------------------------------------------------
// tf32 GEMM: Y = (X @ W^T + bias) * scale.  X,W pre-rounded + k-permuted.
// Tile 128x128xK32, 256 thr (8 warps 4Mx2N), cp.async double-buffered.
// Smem: pitch 32, chunk-XOR swizzle -> conflict-free ld.shared.v4 fragments.
// LAYOUT: 0 flat [M,N] fp32; 1 [B,H,S,Dk] d-permuted tf32; 2 [B,H,Dk,S] key-
// permuted tf32 (V transposed).
// ---------------------------------------------------------------------------
#define GSTAGE (128*32)
#define GEMM_SMEM (4*GSTAGE*4)   // 65536 B

template<int LAYOUT>
__global__ __launch_bounds__(256, 2)
void gemm_tf32(const float* __restrict__ X, const float* __restrict__ W,
               const float* __restrict__ bias, float* __restrict__ Y,
               float scale)
{
    extern __shared__ float sm[];
    float* A = sm;
    float* B = sm + 2 * GSTAGE;
    const int m0 = blockIdx.y * 128, n0 = blockIdx.x * 128;
    const int tid = threadIdx.x, lane = tid & 31, warp = tid >> 5;
    const int g = lane >> 2, tg = lane & 3;
    const int wm = (warp & 3) * 32, wn = (warp >> 2) * 64;
    const uint32_t sA = (uint32_t)__cvta_generic_to_shared(A);
    const uint32_t sB = (uint32_t)__cvta_generic_to_shared(B);
    const float4* A4 = (const float4*)A;
    const float4* B4 = (const float4*)B;

#define G_ISSUE(st, k0)                                                        \
    {                                                                          \
        _Pragma("unroll")                                                      \
        for (int i = 0; i < 4; i++) {                                          \
            int c = tid + i * 256;                                             \
            int row = c >> 3, m = c & 7;                                       \
            int sw = (m ^ ((row & 1) << 2)) << 2;                              \
            cp16(sA + ((st) * GSTAGE + row * 32 + sw) * 4,                     \
                 X + (size_t)(m0 + row) * DMODEL + (k0) + m * 4);              \
            cp16(sB + ((st) * GSTAGE + row * 32 + sw) * 4,                     \
                 W + (size_t)(n0 + row) * DMODEL + (k0) + m * 4);              \
        }                                                                      \
    }

    G_ISSUE(0, 0);  cpcommit();
    G_ISSUE(1, 32); cpcommit();

    float acc[2][8][4];
#pragma unroll
    for (int t = 0; t < 2; t++)
#pragma unroll
        for (int j = 0; j < 8; j++)
#pragma unroll
            for (int c = 0; c < 4; c++) acc[t][j][c] = 0.f;

    for (int kt = 0; kt < 16; kt++) {
        cpwait<1>();
        __syncthreads();
        const int sb = (kt & 1) * (GSTAGE / 4);   // float4 stage base
#pragma unroll
        for (int ksg = 0; ksg < 2; ksg++) {
            // a fragments: rows wm+t*16+g and +8, one float4 each = 2 chunks
            float4 ag[2], ah[2];
#pragma unroll
            for (int t = 0; t < 2; t++) {
                const int r0 = wm + t * 16 + g;
                ag[t] = A4[sb + r0 * 8 + ((ksg * 4 + tg) ^ ((r0 & 1) << 2))];
                const int r1 = r0 + 8;
                ah[t] = A4[sb + r1 * 8 + ((ksg * 4 + tg) ^ ((r1 & 1) << 2))];
            }
#pragma unroll
            for (int j = 0; j < 8; j++) {
                const int rb = wn + j * 8 + g;
                float4 bv = B4[sb + rb * 8 + ((ksg * 4 + tg) ^ ((rb & 1) << 2))];
#pragma unroll
                for (int t = 0; t < 2; t++) {
                    mma_tf32(acc[t][j], U(ag[t].x), U(ah[t].x),
                             U(ag[t].y), U(ah[t].y), U(bv.x), U(bv.y));
                    mma_tf32(acc[t][j], U(ag[t].z), U(ah[t].z),
                             U(ag[t].w), U(ah[t].w), U(bv.z), U(bv.w));
                }
            }
        }
        __syncthreads();
        if (kt + 2 < 16) { G_ISSUE(kt & 1, (kt + 2) * 32); }
        cpcommit();
    }

#pragma unroll
    for (int t = 0; t < 2; t++) {
#pragma unroll
        for (int rr = 0; rr < 2; rr++) {
            const int r = m0 + wm + t * 16 + g + rr * 8;
            const int bb = r >> 12, ss = r & 4095;
#pragma unroll
            for (int j = 0; j < 8; j++) {
                const int n = n0 + wn + j * 8 + 2 * tg;
                float2 bi = *(const float2*)&bias[n];
                float v0 = (acc[t][j][rr * 2 + 0] + bi.x) * scale;
                float v1 = (acc[t][j][rr * 2 + 1] + bi.y) * scale;
                if (LAYOUT == 0) {
                    *(float2*)&Y[(size_t)r * DMODEL + n] = make_float2(v0, v1);
                } else if (LAYOUT == 1) {
                    // d-permuted within 16-blocks; p(d+1)=p(d)+4 for even d
                    const int h = n >> 6, d = n & 63;
                    const int pd = (d & ~15) + 4 * (d & 3) + ((d & 15) >> 2);
                    float* yb = Y + (((size_t)(bb * NHEAD + h)) * SEQ + ss) * DK;
                    yb[pd]     = rnaf(v0);
                    yb[pd + 4] = rnaf(v1);
                } else {
                    // V^T [B,H,Dk,S]: permute the S (key) index
                    const int h = n >> 6, d = n & 63;
                    const int ps = (ss & ~15) + 4 * (ss & 3) + ((ss & 15) >> 2);
                    float* yb = Y + (((size_t)(bb * NHEAD + h)) * DK + d) * SEQ;
                    yb[ps]       = rnaf(v0);
                    yb[ps + SEQ] = rnaf(v1);
                }
            }
        }
    }
#undef G_ISSUE
}

// ---------------------------------------------------------------------------
// tf32 flash attention: 256 thr (8 warps) x 256 query rows, 32 rows/warp
// (2 m16 halves, K/V fragments amortized 2x). Separate persistent Q smem.
// Pitch-64 XOR-swizzled Q/K/V tiles, v4 fragment loads; P pitch 68 permuted.
// ---------------------------------------------------------------------------
#define QROWS 256
#define KVT   (64*64)                       // floats per K or V stage
#define SM_Q   0                            // [256][64] swizzled
#define SM_K   (QROWS*64)                   // [2][64][64] swizzled
#define SM_V   (SM_K + 2*KVT)               // [2][64][64] swizzled
#define SM_P   (SM_V + 2*KVT)               // [256][68] permuted, plain
#define ATT_SMEM ((SM_P + QROWS*68)*4)      // 200704 B

__global__ __launch_bounds__(256, 1)
void attn_kernel()
{
    extern __shared__ float sm[];
    const float4* S4 = (const float4*)sm;
    float* Pb = sm + SM_P;
    const float4* P4 = (const float4*)Pb;   // pitch 17 float4s

    const int bh = blockIdx.y, q0 = blockIdx.x * QROWS;
    const int tid = threadIdx.x, lane = tid & 31, warp = tid >> 5;
    const int g = lane >> 2, tg = lane & 3;
    const int w32 = warp * 32;
    // P-write permuted column base offset per tg: {0,8,1,9}
    const int p0e = ((tg & 1) << 3) + (tg >> 1);

    const float* Qg = g_qh + (size_t)bh * SEQ * DK + (size_t)q0 * DK;
    const float* Kg = g_kh + (size_t)bh * SEQ * DK;
    const float* Vg = g_vh + (size_t)bh * DK * SEQ;

    const uint32_t sQ = (uint32_t)__cvta_generic_to_shared(sm + SM_Q);
    const uint32_t sK = (uint32_t)__cvta_generic_to_shared(sm + SM_K);
    const uint32_t sV = (uint32_t)__cvta_generic_to_shared(sm + SM_V);

    // Q tile fill: 256 rows x 16 chunks, swizzled
#pragma unroll
    for (int i = 0; i < 16; i++) {
        int c = tid + i * 256;
        int row = c >> 4, m = c & 15;
        int sw = (m ^ ((row & 1) << 2)) << 2;
        cp16(sQ + (row * 64 + sw) * 4, Qg + (size_t)row * DK + m * 4);
    }
    cpcommit();

#define KV_ISSUE(st, ktile)                                                    \
    {                                                                          \
        _Pragma("unroll")                                                      \
        for (int i = 0; i < 8; i++) {                                          \
            int c = tid + i * 256;                                             \
            int r = (c >> 4) & 63, m = c & 15;                                 \
            int sw = (m ^ ((r & 1) << 2)) << 2;                                \
            if (c < 1024)                                                      \
                cp16(sK + ((st) * KVT + r * 64 + sw) * 4,                      \
                     Kg + ((size_t)(ktile) * 64 + r) * DK + m * 4);            \
            else                                                               \
                cp16(sV + ((st) * KVT + r * 64 + sw) * 4,                      \
                     Vg + (size_t)r * SEQ + (ktile) * 64 + m * 4);             \
        }                                                                      \
    }

    KV_ISSUE(0, 0); cpcommit();
    KV_ISSUE(1, 1); cpcommit();

    float o[2][8][4];
    float mx[2][2], li[2][2];
#pragma unroll
    for (int h = 0; h < 2; h++) {
        mx[h][0] = -1e30f; mx[h][1] = -1e30f; li[h][0] = 0.f; li[h][1] = 0.f;
#pragma unroll
        for (int nt = 0; nt < 8; nt++)
#pragma unroll
            for (int c = 0; c < 4; c++) o[h][nt][c] = 0.f;
    }

    const int q4 = SM_Q / 4, k4 = SM_K / 4, v4 = SM_V / 4;

    for (int kt = 0; kt < SEQ / 64; kt++) {
        cpwait<1>();
        __syncthreads();
        const int kb = k4 + (kt & 1) * (KVT / 4);
        const int vb = v4 + (kt & 1) * (KVT / 4);

        // ---- S = Q @ K^T (both halves share K fragments) ----
        float sc[2][8][4];
#pragma unroll
        for (int h = 0; h < 2; h++)
#pragma unroll
            for (int nt = 0; nt < 8; nt++)
#pragma unroll
                for (int c = 0; c < 4; c++) sc[h][nt][c] = 0.f;

#pragma unroll
        for (int ksg = 0; ksg < 4; ksg++) {
            const int cc = ksg * 4 + tg;
            float4 qg[2], qh8[2];
#pragma unroll
            for (int h = 0; h < 2; h++) {
                const int r0 = w32 + h * 16 + g;
                qg[h]  = S4[q4 + r0 * 16 + (cc ^ ((r0 & 1) << 2))];
                const int r1 = r0 + 8;
                qh8[h] = S4[q4 + r1 * 16 + (cc ^ ((r1 & 1) << 2))];
            }
#pragma unroll
            for (int nt = 0; nt < 8; nt++) {
                const int rk = nt * 8 + g;
                float4 kv = S4[kb + rk * 16 + (cc ^ ((rk & 1) << 2))];
#pragma unroll
                for (int h = 0; h < 2; h++) {
                    mma_tf32(sc[h][nt], U(qg[h].x), U(qh8[h].x),
                             U(qg[h].y), U(qh8[h].y), U(kv.x), U(kv.y));
                    mma_tf32(sc[h][nt], U(qg[h].z), U(qh8[h].z),
                             U(qg[h].w), U(qh8[h].w), U(kv.z), U(kv.w));
                }
            }
        }

        // ---- Online softmax per half; P written permuted ----
#pragma unroll
        for (int h = 0; h < 2; h++) {
            float m0 = -1e30f, m1 = -1e30f;
#pragma unroll
            for (int nt = 0; nt < 8; nt++) {
                m0 = fmaxf(m0, fmaxf(sc[h][nt][0], sc[h][nt][1]));
                m1 = fmaxf(m1, fmaxf(sc[h][nt][2], sc[h][nt][3]));
            }
            m0 = fmaxf(m0, __shfl_xor_sync(0xffffffffu, m0, 1));
            m0 = fmaxf(m0, __shfl_xor_sync(0xffffffffu, m0, 2));
            m1 = fmaxf(m1, __shfl_xor_sync(0xffffffffu, m1, 1));
            m1 = fmaxf(m1, __shfl_xor_sync(0xffffffffu, m1, 2));

            const float mn0 = fmaxf(mx[h][0], m0), mn1 = fmaxf(mx[h][1], m1);
            const float c0 = __expf(mx[h][0] - mn0), c1 = __expf(mx[h][1] - mn1);
            mx[h][0] = mn0; mx[h][1] = mn1;

            float s0 = 0.f, s1 = 0.f;
            const int rA = w32 + h * 16 + g;
#pragma unroll
            for (int nt = 0; nt < 8; nt++) {
                float p00 = __expf(sc[h][nt][0] - mn0);
                float p01 = __expf(sc[h][nt][1] - mn0);
                float p10 = __expf(sc[h][nt][2] - mn1);
                float p11 = __expf(sc[h][nt][3] - mn1);
                s0 += p00 + p01;
                s1 += p10 + p11;
                const int pos = (nt >> 1) * 16 + p0e + 2 * (nt & 1);
                Pb[rA * 68 + pos]           = rnaf(p00);
                Pb[rA * 68 + pos + 4]       = rnaf(p01);
                Pb[(rA + 8) * 68 + pos]     = rnaf(p10);
                Pb[(rA + 8) * 68 + pos + 4] = rnaf(p11);
            }
            s0 += __shfl_xor_sync(0xffffffffu, s0, 1);
            s0 += __shfl_xor_sync(0xffffffffu, s0, 2);
            s1 += __shfl_xor_sync(0xffffffffu, s1, 1);
            s1 += __shfl_xor_sync(0xffffffffu, s1, 2);
            li[h][0] = li[h][0] * c0 + s0;
            li[h][1] = li[h][1] * c1 + s1;
#pragma unroll
            for (int nt = 0; nt < 8; nt++) {
                o[h][nt][0] *= c0; o[h][nt][1] *= c0;
                o[h][nt][2] *= c1; o[h][nt][3] *= c1;
            }
        }
        __syncwarp();   // P rows are warp-private

        // ---- O += P @ V (V fragments shared across halves) ----
#pragma unroll
        for (int ksg = 0; ksg < 4; ksg++) {
            const int cc = ksg * 4 + tg;
            float4 pg[2], ph8[2];
#pragma unroll
            for (int h = 0; h < 2; h++) {
                const int r0 = w32 + h * 16 + g;
                pg[h]  = P4[r0 * 17 + cc];
                ph8[h] = P4[(r0 + 8) * 17 + cc];
            }
#pragma unroll
            for (int nt = 0; nt < 8; nt++) {
                const int rv = nt * 8 + g;
                float4 vv = S4[vb + rv * 16 + (cc ^ ((rv & 1) << 2))];
#pragma unroll
                for (int h = 0; h < 2; h++) {
                    mma_tf32(o[h][nt], U(pg[h].x), U(ph8[h].x),
                             U(pg[h].y), U(ph8[h].y), U(vv.x), U(vv.y));
                    mma_tf32(o[h][nt], U(pg[h].z), U(ph8[h].z),
                             U(pg[h].w), U(ph8[h].w), U(vv.z), U(vv.w));
                }
            }
        }
        __syncthreads();   // all warps done with stage before refill
        if (kt + 2 < SEQ / 64) { KV_ISSUE(kt & 1, kt + 2); }
        cpcommit();
    }

    // Epilogue: normalize, round, write [B,S,D] with D permuted (feeds O-GEMM)
    const int bb = bh >> 3, hh = bh & 7;
    float* Og = g_att + ((size_t)bb * SEQ + q0) * DMODEL + hh * DK;
#pragma unroll
    for (int h = 0; h < 2; h++) {
#pragma unroll
        for (int rr = 0; rr < 2; rr++) {
            const float inv = 1.0f / li[h][rr];
            const int row = w32 + h * 16 + g + rr * 8;
#pragma unroll
            for (int nt = 0; nt < 8; nt++) {
                const int pos = (nt >> 1) * 16 + p0e + 2 * (nt & 1);
                Og[(size_t)row * DMODEL + pos]
                    = rnaf(o[h][nt][rr * 2 + 0] * inv);
                Og[(size_t)row * DMODEL + pos + 4]
                    = rnaf(o[h][nt][rr * 2 + 1] * inv);
            }
        }
    }
#undef KV_ISSUE
}

// ---------------------------------------------------------------------------
extern "C" void kernel_launch(void* const* d_in, const int* in_sizes, int n_in,
                              void* d_out, int out_size)
{
    const float* q  = (const float*)d_in[0];
    const float* k  = (const float*)d_in[1];
    const float* v  = (const float*)d_in[2];
    const float* wq = (const float*)d_in[3];
    const float* bq = (const float*)d_in[4];
    const float* wk = (const float*)d_in[5];
    const float* bk = (const float*)d_in[6];
    const float* wv = (const float*)d_in[7];
    const float* bv = (const float*)d_in[8];
    const float* wo = (const float*)d_in[9];
    const float* bo = (const float*)d_in[10];

    float *qh, *kh, *vh, *att, *rq, *rk, *rv, *rw;
    cudaGetSymbolAddress((void**)&qh,  g_qh);
    cudaGetSymbolAddress((void**)&kh,  g_kh);
    cudaGetSymbolAddress((void**)&vh,  g_vh);
    cudaGetSymbolAddress((void**)&att, g_att);
    cudaGetSymbolAddress((void**)&rq,  g_rq);
    cudaGetSymbolAddress((void**)&rk,  g_rk);
    cudaGetSymbolAddress((void**)&rv,  g_rv);
    cudaGetSymbolAddress((void**)&rw,  g_rw);

    cudaFuncSetAttribute(gemm_tf32<0>,
        cudaFuncAttributeMaxDynamicSharedMemorySize, GEMM_SMEM);
    cudaFuncSetAttribute(gemm_tf32<1>,
        cudaFuncAttributeMaxDynamicSharedMemorySize, GEMM_SMEM);
    cudaFuncSetAttribute(gemm_tf32<2>,
        cudaFuncAttributeMaxDynamicSharedMemorySize, GEMM_SMEM);
    cudaFuncSetAttribute(attn_kernel,
        cudaFuncAttributeMaxDynamicSharedMemorySize, ATT_SMEM);

    const int DD = DMODEL * DMODEL;
    const int n4x = MTOT * DMODEL / 4;   // 1048576
    const int n4w = DD / 4;              // 65536

    round3_kernel<<<dim3(256, 3), 256>>>((const float4*)q, (const float4*)k,
                                         (const float4*)v, rq, rk, rv, n4x);
    round4_kernel<<<dim3(128, 4), 256>>>((const float4*)wq, (const float4*)wk,
                                         (const float4*)wv, (const float4*)wo,
                                         rw, n4w);

    dim3 gg(DMODEL / 128, MTOT / 128);   // (4, 64)
    // scale 1/sqrt(Dk)=0.125 fused into Q projection
    gemm_tf32<1><<<gg, 256, GEMM_SMEM>>>(rq, rw + 0 * DD, bq, qh, 0.125f);
    gemm_tf32<1><<<gg, 256, GEMM_SMEM>>>(rk, rw + 1 * DD, bk, kh, 1.0f);
    gemm_tf32<2><<<gg, 256, GEMM_SMEM>>>(rv, rw + 2 * DD, bv, vh, 1.0f);

    attn_kernel<<<dim3(SEQ / QROWS, BATCH * NHEAD), 256, ATT_SMEM>>>();

    gemm_tf32<0><<<gg, 256, GEMM_SMEM>>>(att, rw + 3 * DD, bo,
                                         (float*)d_out, 1.0f);
}

// round 6
// speedup vs baseline: 1.1163x; 1.1163x over previous
#include <cuda_runtime.h>
#include <cstdint>

#define DMODEL 512
#define NHEAD  8
#define DK     64
#define BATCH  2
#define SEQ    4096
#define MTOT   (BATCH*SEQ)   // 8192

// Scratch (static device arrays — no runtime allocation)
__device__ float g_qh[(size_t)BATCH*NHEAD*SEQ*DK];   // [B,H,S,Dk], tf32, *(log2e/8)
__device__ float g_kh[(size_t)BATCH*NHEAD*SEQ*DK];   // [B,H,S,Dk], tf32
__device__ float g_vh[(size_t)BATCH*NHEAD*SEQ*DK];   // [B,H,Dk,S] TRANSPOSED, tf32
__device__ float g_att[(size_t)MTOT*DMODEL];         // [B,S,D], tf32-rounded
__device__ float g_rq[(size_t)MTOT*DMODEL];          // tf32-rounded inputs
__device__ float g_rk[(size_t)MTOT*DMODEL];
__device__ float g_rv[(size_t)MTOT*DMODEL];
__device__ float g_rw[(size_t)4*DMODEL*DMODEL];      // tf32-rounded weights

// ---------------------------------------------------------------------------
__device__ __forceinline__ uint32_t f2tf(float f) {
    uint32_t u;
    asm("cvt.rna.tf32.f32 %0, %1;" : "=r"(u) : "f"(f));
    return u;
}
__device__ __forceinline__ float rnaf(float f) { return __uint_as_float(f2tf(f)); }

__device__ __forceinline__ float ex2(float x) {
    float r;
    asm("ex2.approx.ftz.f32 %0, %1;" : "=f"(r) : "f"(x));
    return r;
}

__device__ __forceinline__ void mma_tf32(float* d, const uint32_t* a,
                                         uint32_t b0, uint32_t b1) {
    asm volatile(
        "mma.sync.aligned.m16n8k8.row.col.f32.tf32.tf32.f32 "
        "{%0,%1,%2,%3}, {%4,%5,%6,%7}, {%8,%9}, {%0,%1,%2,%3};\n"
        : "+f"(d[0]), "+f"(d[1]), "+f"(d[2]), "+f"(d[3])
        : "r"(a[0]), "r"(a[1]), "r"(a[2]), "r"(a[3]), "r"(b0), "r"(b1));
}

__device__ __forceinline__ void cp16(uint32_t saddr, const void* g) {
    asm volatile("cp.async.cg.shared.global [%0], [%1], 16;\n"
                 :: "r"(saddr), "l"(g));
}
__device__ __forceinline__ void cpcommit() {
    asm volatile("cp.async.commit_group;\n");
}
template<int N> __device__ __forceinline__ void cpwait() {
    asm volatile("cp.async.wait_group %0;\n" :: "n"(N));
}

// ---------------------------------------------------------------------------
// Batched rna-round to tf32 (plain layout — R4 version, permute reverted)
// ---------------------------------------------------------------------------
__global__ void round3_kernel(const float4* __restrict__ s0,
                              const float4* __restrict__ s1,
                              const float4* __restrict__ s2,
                              float4* __restrict__ d0,
                              float4* __restrict__ d1,
                              float4* __restrict__ d2, int n4)
{
    const float4* s = (blockIdx.y == 0) ? s0 : (blockIdx.y == 1) ? s1 : s2;
    float4*       d = (blockIdx.y == 0) ? d0 : (blockIdx.y == 1) ? d1 : d2;
    for (int i = blockIdx.x * blockDim.x + threadIdx.x; i < n4;
         i += gridDim.x * blockDim.x) {
        float4 v = s[i];
        v.x = rnaf(v.x); v.y = rnaf(v.y); v.z = rnaf(v.z); v.w = rnaf(v.w);
        d[i] = v;
    }
}

__global__ void round4_kernel(const float4* __restrict__ s0,
                              const float4* __restrict__ s1,
                              const float4* __restrict__ s2,
                              const float4* __restrict__ s3,
                              float4* __restrict__ dst, int n4)
{
    const float4* s = (blockIdx.y == 0) ? s0 : (blockIdx.y == 1) ? s1
                    : (blockIdx.y == 2) ? s2 : s3;
    float4* d = dst + (size_t)blockIdx.y * n4;
    for (int i = blockIdx.x * blockDim.x + threadIdx.x; i < n4;
         i += gridDim.x * blockDim.x) {
        float4 v = s[i];
        v.x = rnaf(v.x); v.y = rnaf(v.y); v.z = rnaf(v.z); v.w = rnaf(v.w);
        d[i] = v;
    }
}

// ---------------------------------------------------------------------------
// tf32 tensor-core GEMM: Y = (X @ W^T + bias) * scale   (R4 version, reverted)
// ---------------------------------------------------------------------------
#define GP 36
#define GSTAGE (128*GP)
#define GEMM_SMEM (4*GSTAGE*4)   // 73728 B

template<int LAYOUT>
__global__ __launch_bounds__(256)
void gemm_tf32(const float* __restrict__ X, const float* __restrict__ W,
               const float* __restrict__ bias, float* __restrict__ Y,
               float scale)
{
    extern __shared__ float sm[];
    float* A = sm;
    float* B = sm + 2 * GSTAGE;
    const int m0 = blockIdx.y * 128, n0 = blockIdx.x * 128;
    const int tid = threadIdx.x, lane = tid & 31, warp = tid >> 5;
    const int g = lane >> 2, tg = lane & 3;
    const int wm = (warp & 3) * 32, wn = (warp >> 2) * 64;
    const uint32_t sA = (uint32_t)__cvta_generic_to_shared(A);
    const uint32_t sB = (uint32_t)__cvta_generic_to_shared(B);

#define G_ISSUE(st, k0)                                                        \
    {                                                                          \
        _Pragma("unroll")                                                      \
        for (int i = 0; i < 4; i++) {                                          \
            int c = tid + i * 256;                                             \
            int row = c >> 3, kc = (c & 7) * 4;                                \
            cp16(sA + ((st) * GSTAGE + row * GP + kc) * 4,                     \
                 X + (size_t)(m0 + row) * DMODEL + (k0) + kc);                 \
            cp16(sB + ((st) * GSTAGE + row * GP + kc) * 4,                     \
                 W + (size_t)(n0 + row) * DMODEL + (k0) + kc);                 \
        }                                                                      \
    }

    G_ISSUE(0, 0);  cpcommit();
    G_ISSUE(1, 32); cpcommit();

    float acc[2][8][4];
#pragma unroll
    for (int t = 0; t < 2; t++)
#pragma unroll
        for (int j = 0; j < 8; j++)
#pragma unroll
            for (int c = 0; c < 4; c++) acc[t][j][c] = 0.f;

    for (int kt = 0; kt < 16; kt++) {
        cpwait<1>();
        __syncthreads();
        const float* As = A + (kt & 1) * GSTAGE;
        const float* Bs = B + (kt & 1) * GSTAGE;
#pragma unroll
        for (int ks = 0; ks < 4; ks++) {
            const int k = ks * 8;
            uint32_t a[2][4];
#pragma unroll
            for (int t = 0; t < 2; t++) {
                const int r = wm + t * 16;
                a[t][0] = __float_as_uint(As[(r + g    ) * GP + k + tg]);
                a[t][1] = __float_as_uint(As[(r + g + 8) * GP + k + tg]);
                a[t][2] = __float_as_uint(As[(r + g    ) * GP + k + tg + 4]);
                a[t][3] = __float_as_uint(As[(r + g + 8) * GP + k + tg + 4]);
            }
#pragma unroll
            for (int j = 0; j < 8; j++) {
                uint32_t b0 = __float_as_uint(Bs[(wn + j * 8 + g) * GP + k + tg]);
                uint32_t b1 = __float_as_uint(Bs[(wn + j * 8 + g) * GP + k + tg + 4]);
                mma_tf32(acc[0][j], a[0], b0, b1);
                mma_tf32(acc[1][j], a[1], b0, b1);
            }
        }
        __syncthreads();
        if (kt + 2 < 16) { G_ISSUE(kt & 1, (kt + 2) * 32); }
        cpcommit();
    }

#pragma unroll
    for (int t = 0; t < 2; t++) {
#pragma unroll
        for (int rr = 0; rr < 2; rr++) {
            const int r = m0 + wm + t * 16 + g + rr * 8;
            const int bb = r >> 12, ss = r & 4095;
#pragma unroll
            for (int j = 0; j < 8; j++) {
                const int n = n0 + wn + j * 8 + 2 * tg;
                float2 bi = *(const float2*)&bias[n];
                float v0 = (acc[t][j][rr * 2 + 0] + bi.x) * scale;
                float v1 = (acc[t][j][rr * 2 + 1] + bi.y) * scale;
                if (LAYOUT == 0) {
                    *(float2*)&Y[(size_t)r * DMODEL + n] = make_float2(v0, v1);
                } else if (LAYOUT == 1) {
                    const int h = n >> 6, d = n & 63;
                    *(float2*)&Y[(((size_t)(bb * NHEAD + h)) * SEQ + ss) * DK + d]
                        = make_float2(rnaf(v0), rnaf(v1));
                } else {
                    const int h = n >> 6, d = n & 63;
                    Y[(((size_t)(bb * NHEAD + h)) * DK + d    ) * SEQ + ss] = rnaf(v0);
                    Y[(((size_t)(bb * NHEAD + h)) * DK + d + 1) * SEQ + ss] = rnaf(v1);
                }
            }
        }
    }
#undef G_ISSUE
}

// ---------------------------------------------------------------------------
// tf32 flash attention, occupancy-tuned: 256 thr (8 warps) x 128 query rows,
// 16 rows/warp, Q fragments in registers, 104KB smem -> 2 CTAs/SM =
// 16 warps/SM (4/SMSP) so MUFU/LDS chains hide under MMA across warps.
// Softmax in exp2 domain (log2e folded into Q projection scale).
// ---------------------------------------------------------------------------
#define AP 68
#define KVT (64*AP)
#define QROWS 128
#define ATT_SMEM ((4*KVT + QROWS*AP)*4)   // 104448 B

__global__ __launch_bounds__(256, 2)
void attn_kernel()
{
    extern __shared__ float sm[];
    float* Kb = sm;              // [2][64][AP]  K[key][d]
    float* Vb = sm + 2 * KVT;    // [2][64][AP]  V^T[d][key]
    float* Pb = sm + 4 * KVT;    // [128][AP]    Q then P (warp-private rows)

    const int bh = blockIdx.y, q0 = blockIdx.x * QROWS;
    const int tid = threadIdx.x, lane = tid & 31, warp = tid >> 5;
    const int g = lane >> 2, tg = lane & 3;
    const int w16 = warp * 16;

    const float* Qg = g_qh + (size_t)bh * SEQ * DK + (size_t)q0 * DK;
    const float* Kg = g_kh + (size_t)bh * SEQ * DK;
    const float* Vg = g_vh + (size_t)bh * DK * SEQ;

    const uint32_t sK = (uint32_t)__cvta_generic_to_shared(Kb);
    const uint32_t sV = (uint32_t)__cvta_generic_to_shared(Vb);
    const uint32_t sP = (uint32_t)__cvta_generic_to_shared(Pb);

    // Q tile: 128 rows x 64 = 2048 16B-chunks over 256 threads
#pragma unroll
    for (int i = 0; i < 8; i++) {
        int c = tid + i * 256;
        int row = c >> 4, kc = (c & 15) * 4;
        cp16(sP + (row * AP + kc) * 4, Qg + (size_t)row * DK + kc);
    }
    cpcommit();

#define KV_ISSUE(st, ktile)                                                    \
    {                                                                          \
        _Pragma("unroll")                                                      \
        for (int i = 0; i < 8; i++) {                                          \
            int c = tid + i * 256;                                             \
            int r = (c >> 4) & 63, kc = (c & 15) * 4;                          \
            if (c < 1024)                                                      \
                cp16(sK + ((st) * KVT + r * AP + kc) * 4,                      \
                     Kg + ((size_t)(ktile) * 64 + r) * DK + kc);               \
            else                                                               \
                cp16(sV + ((st) * KVT + r * AP + kc) * 4,                      \
                     Vg + (size_t)r * SEQ + (ktile) * 64 + kc);                \
        }                                                                      \
    }

    KV_ISSUE(0, 0); cpcommit();
    KV_ISSUE(1, 1); cpcommit();

    cpwait<2>();
    __syncthreads();

    // Q fragments in registers (m16 x k64)
    uint32_t qa[8][4];
#pragma unroll
    for (int ks = 0; ks < 8; ks++) {
        qa[ks][0] = __float_as_uint(Pb[(w16 + g    ) * AP + ks * 8 + tg]);
        qa[ks][1] = __float_as_uint(Pb[(w16 + g + 8) * AP + ks * 8 + tg]);
        qa[ks][2] = __float_as_uint(Pb[(w16 + g    ) * AP + ks * 8 + tg + 4]);
        qa[ks][3] = __float_as_uint(Pb[(w16 + g + 8) * AP + ks * 8 + tg + 4]);
    }

    float o[8][4];
#pragma unroll
    for (int nt = 0; nt < 8; nt++)
#pragma unroll
        for (int c = 0; c < 4; c++) o[nt][c] = 0.f;
    float m0 = -1e30f, m1 = -1e30f, l0 = 0.f, l1 = 0.f;

    for (int kt = 0; kt < SEQ / 64; kt++) {
        cpwait<1>();
        __syncthreads();
        const float* Ks = Kb + (kt & 1) * KVT;
        const float* Vs = Vb + (kt & 1) * KVT;

        // S = Q @ K^T (scores already in log2e units)
        float sc[8][4];
#pragma unroll
        for (int nt = 0; nt < 8; nt++)
#pragma unroll
            for (int c = 0; c < 4; c++) sc[nt][c] = 0.f;

#pragma unroll
        for (int nt = 0; nt < 8; nt++) {
#pragma unroll
            for (int ks = 0; ks < 8; ks++) {
                uint32_t b0 = __float_as_uint(Ks[(nt * 8 + g) * AP + ks * 8 + tg]);
                uint32_t b1 = __float_as_uint(Ks[(nt * 8 + g) * AP + ks * 8 + tg + 4]);
                mma_tf32(sc[nt], qa[ks], b0, b1);
            }
        }

        // Online softmax, exp2 domain
        float mx0 = -1e30f, mx1 = -1e30f;
#pragma unroll
        for (int nt = 0; nt < 8; nt++) {
            mx0 = fmaxf(mx0, fmaxf(sc[nt][0], sc[nt][1]));
            mx1 = fmaxf(mx1, fmaxf(sc[nt][2], sc[nt][3]));
        }
        mx0 = fmaxf(mx0, __shfl_xor_sync(0xffffffffu, mx0, 1));
        mx0 = fmaxf(mx0, __shfl_xor_sync(0xffffffffu, mx0, 2));
        mx1 = fmaxf(mx1, __shfl_xor_sync(0xffffffffu, mx1, 1));
        mx1 = fmaxf(mx1, __shfl_xor_sync(0xffffffffu, mx1, 2));

        const float mn0 = fmaxf(m0, mx0), mn1 = fmaxf(m1, mx1);
        const float c0 = ex2(m0 - mn0), c1 = ex2(m1 - mn1);
        m0 = mn0; m1 = mn1;

        float s0 = 0.f, s1 = 0.f;
        const int rA = w16 + g;
#pragma unroll
        for (int nt = 0; nt < 8; nt++) {
            float p00 = ex2(sc[nt][0] - mn0);
            float p01 = ex2(sc[nt][1] - mn0);
            float p10 = ex2(sc[nt][2] - mn1);
            float p11 = ex2(sc[nt][3] - mn1);
            s0 += p00 + p01;
            s1 += p10 + p11;
            *(float2*)&Pb[(rA    ) * AP + nt * 8 + 2 * tg]
                = make_float2(rnaf(p00), rnaf(p01));
            *(float2*)&Pb[(rA + 8) * AP + nt * 8 + 2 * tg]
                = make_float2(rnaf(p10), rnaf(p11));
        }
        s0 += __shfl_xor_sync(0xffffffffu, s0, 1);
        s0 += __shfl_xor_sync(0xffffffffu, s0, 2);
        s1 += __shfl_xor_sync(0xffffffffu, s1, 1);
        s1 += __shfl_xor_sync(0xffffffffu, s1, 2);
        l0 = l0 * c0 + s0;
        l1 = l1 * c1 + s1;
#pragma unroll
        for (int nt = 0; nt < 8; nt++) {
            o[nt][0] *= c0; o[nt][1] *= c0;
            o[nt][2] *= c1; o[nt][3] *= c1;
        }
        __syncwarp();   // P rows are warp-private

        // O += P @ V
#pragma unroll
        for (int ks = 0; ks < 8; ks++) {
            uint32_t pa[4];
            pa[0] = __float_as_uint(Pb[(w16 + g    ) * AP + ks * 8 + tg]);
            pa[1] = __float_as_uint(Pb[(w16 + g + 8) * AP + ks * 8 + tg]);
            pa[2] = __float_as_uint(Pb[(w16 + g    ) * AP + ks * 8 + tg + 4]);
            pa[3] = __float_as_uint(Pb[(w16 + g + 8) * AP + ks * 8 + tg + 4]);
#pragma unroll
            for (int nt = 0; nt < 8; nt++) {
                uint32_t b0 = __float_as_uint(Vs[(nt * 8 + g) * AP + ks * 8 + tg]);
                uint32_t b1 = __float_as_uint(Vs[(nt * 8 + g) * AP + ks * 8 + tg + 4]);
                mma_tf32(o[nt], pa, b0, b1);
            }
        }
        __syncthreads();   // all warps done with stage before refill
        if (kt + 2 < SEQ / 64) { KV_ISSUE(kt & 1, kt + 2); }
        cpcommit();
    }

    // Epilogue: normalize, round (feeds tf32 O-GEMM), write [B,S,D]
    const int bb = bh >> 3, hh = bh & 7;
    float* Og = g_att + ((size_t)bb * SEQ + q0) * DMODEL + hh * DK;
    const float inv0 = 1.0f / l0, inv1 = 1.0f / l1;
#pragma unroll
    for (int nt = 0; nt < 8; nt++) {
        *(float2*)&Og[(size_t)(w16 + g    ) * DMODEL + nt * 8 + 2 * tg]
            = make_float2(rnaf(o[nt][0] * inv0), rnaf(o[nt][1] * inv0));
        *(float2*)&Og[(size_t)(w16 + g + 8) * DMODEL + nt * 8 + 2 * tg]
            = make_float2(rnaf(o[nt][2] * inv1), rnaf(o[nt][3] * inv1));
    }
#undef KV_ISSUE
}

// ---------------------------------------------------------------------------
extern "C" void kernel_launch(void* const* d_in, const int* in_sizes, int n_in,
                              void* d_out, int out_size)
{
    const float* q  = (const float*)d_in[0];
    const float* k  = (const float*)d_in[1];
    const float* v  = (const float*)d_in[2];
    const float* wq = (const float*)d_in[3];
    const float* bq = (const float*)d_in[4];
    const float* wk = (const float*)d_in[5];
    const float* bk = (const float*)d_in[6];
    const float* wv = (const float*)d_in[7];
    const float* bv = (const float*)d_in[8];
    const float* wo = (const float*)d_in[9];
    const float* bo = (const float*)d_in[10];

    float *qh, *kh, *vh, *att, *rq, *rk, *rv, *rw;
    cudaGetSymbolAddress((void**)&qh,  g_qh);
    cudaGetSymbolAddress((void**)&kh,  g_kh);
    cudaGetSymbolAddress((void**)&vh,  g_vh);
    cudaGetSymbolAddress((void**)&att, g_att);
    cudaGetSymbolAddress((void**)&rq,  g_rq);
    cudaGetSymbolAddress((void**)&rk,  g_rk);
    cudaGetSymbolAddress((void**)&rv,  g_rv);
    cudaGetSymbolAddress((void**)&rw,  g_rw);

    cudaFuncSetAttribute(gemm_tf32<0>,
        cudaFuncAttributeMaxDynamicSharedMemorySize, GEMM_SMEM);
    cudaFuncSetAttribute(gemm_tf32<1>,
        cudaFuncAttributeMaxDynamicSharedMemorySize, GEMM_SMEM);
    cudaFuncSetAttribute(gemm_tf32<2>,
        cudaFuncAttributeMaxDynamicSharedMemorySize, GEMM_SMEM);
    cudaFuncSetAttribute(attn_kernel,
        cudaFuncAttributeMaxDynamicSharedMemorySize, ATT_SMEM);

    const int DD = DMODEL * DMODEL;
    const int n4x = MTOT * DMODEL / 4;   // 1048576
    const int n4w = DD / 4;              // 65536

    // L1: round inputs; L2: round weights
    round3_kernel<<<dim3(256, 3), 256>>>((const float4*)q, (const float4*)k,
                                         (const float4*)v, (float4*)rq,
                                         (float4*)rk, (float4*)rv, n4x);
    round4_kernel<<<dim3(128, 4), 256>>>((const float4*)wq, (const float4*)wk,
                                         (const float4*)wv, (const float4*)wo,
                                         (float4*)rw, n4w);

    dim3 gg(DMODEL / 128, MTOT / 128);   // (4, 64)
    // Q scale: 1/sqrt(Dk) * log2(e) — softmax runs in exp2 domain
    const float QSCALE = 0.125f * 1.4426950408889634f;
    gemm_tf32<1><<<gg, 256, GEMM_SMEM>>>(rq, rw + 0 * DD, bq, qh, QSCALE);
    gemm_tf32<1><<<gg, 256, GEMM_SMEM>>>(rk, rw + 1 * DD, bk, kh, 1.0f);
    gemm_tf32<2><<<gg, 256, GEMM_SMEM>>>(rv, rw + 2 * DD, bv, vh, 1.0f);

    // L6: attention (profiled by ncu -s 5 -c 1)
    attn_kernel<<<dim3(SEQ / QROWS, BATCH * NHEAD), 256, ATT_SMEM>>>();

    // L7: output projection
    gemm_tf32<0><<<gg, 256, GEMM_SMEM>>>(att, rw + 3 * DD, bo,
                                         (float*)d_out, 1.0f);
}

// round 8
// speedup vs baseline: 2.1983x; 1.9693x over previous
#include <cuda_runtime.h>
#include <cuda_fp16.h>
#include <cstdint>

#define DMODEL 512
#define NHEAD  8
#define DK     64
#define BATCH  2
#define SEQ    4096
#define MTOT   (BATCH*SEQ)   // 8192

// Scratch (static device arrays — no runtime allocation). All fp16.
__device__ __half g_qh[(size_t)BATCH*NHEAD*SEQ*DK];   // [B,H,S,Dk], *(log2e/8)
__device__ __half g_kh[(size_t)BATCH*NHEAD*SEQ*DK];   // [B,H,S,Dk]
__device__ __half g_vh[(size_t)BATCH*NHEAD*SEQ*DK];   // [B,H,Dk,S] TRANSPOSED
__device__ __half g_att[(size_t)MTOT*DMODEL];         // [B,S,D]
__device__ __half g_rq[(size_t)MTOT*DMODEL];          // fp16 inputs
__device__ __half g_rk[(size_t)MTOT*DMODEL];
__device__ __half g_rv[(size_t)MTOT*DMODEL];
__device__ __half g_rw[(size_t)4*DMODEL*DMODEL];      // fp16 weights

// ---------------------------------------------------------------------------
__device__ __forceinline__ float ex2(float x) {
    float r;
    asm("ex2.approx.ftz.f32 %0, %1;" : "=f"(r) : "f"(x));
    return r;
}

// fp16 m16n8k16 MMA, fp32 accumulate
__device__ __forceinline__ void mma_f16(float* d, const uint32_t* a,
                                        uint32_t b0, uint32_t b1) {
    asm volatile(
        "mma.sync.aligned.m16n8k16.row.col.f32.f16.f16.f32 "
        "{%0,%1,%2,%3}, {%4,%5,%6,%7}, {%8,%9}, {%0,%1,%2,%3};\n"
        : "+f"(d[0]), "+f"(d[1]), "+f"(d[2]), "+f"(d[3])
        : "r"(a[0]), "r"(a[1]), "r"(a[2]), "r"(a[3]), "r"(b0), "r"(b1));
}

__device__ __forceinline__ void cp16(uint32_t saddr, const void* g) {
    asm volatile("cp.async.cg.shared.global [%0], [%1], 16;\n"
                 :: "r"(saddr), "l"(g));
}
__device__ __forceinline__ void cpcommit() {
    asm volatile("cp.async.commit_group;\n");
}
template<int N> __device__ __forceinline__ void cpwait() {
    asm volatile("cp.async.wait_group %0;\n" :: "n"(N));
}
#define LD32(p) (*(const uint32_t*)(p))

// ---------------------------------------------------------------------------
// Batched f32 -> f16 conversion (rn)
// ---------------------------------------------------------------------------
__global__ void conv3_kernel(const float4* __restrict__ s0,
                             const float4* __restrict__ s1,
                             const float4* __restrict__ s2,
                             __half2* __restrict__ d0,
                             __half2* __restrict__ d1,
                             __half2* __restrict__ d2, int n4)
{
    const float4* s = (blockIdx.y == 0) ? s0 : (blockIdx.y == 1) ? s1 : s2;
    __half2*      d = (blockIdx.y == 0) ? d0 : (blockIdx.y == 1) ? d1 : d2;
    for (int i = blockIdx.x * blockDim.x + threadIdx.x; i < n4;
         i += gridDim.x * blockDim.x) {
        float4 v = s[i];
        d[i * 2 + 0] = __floats2half2_rn(v.x, v.y);
        d[i * 2 + 1] = __floats2half2_rn(v.z, v.w);
    }
}

__global__ void conv4_kernel(const float4* __restrict__ s0,
                             const float4* __restrict__ s1,
                             const float4* __restrict__ s2,
                             const float4* __restrict__ s3,
                             __half2* __restrict__ dst, int n4)
{
    const float4* s = (blockIdx.y == 0) ? s0 : (blockIdx.y == 1) ? s1
                    : (blockIdx.y == 2) ? s2 : s3;
    __half2* d = dst + (size_t)blockIdx.y * n4 * 2;
    for (int i = blockIdx.x * blockDim.x + threadIdx.x; i < n4;
         i += gridDim.x * blockDim.x) {
        float4 v = s[i];
        d[i * 2 + 0] = __floats2half2_rn(v.x, v.y);
        d[i * 2 + 1] = __floats2half2_rn(v.z, v.w);
    }
}

// ---------------------------------------------------------------------------
// fp16 tensor-core GEMM: Y = (X @ W^T + bias) * scale
// X:[8192,512] W:[512,512] row-major fp16. Tile 128x128, k64 stages (8),
// 256 thr (8 warps, 4Mx2N), cp.async double-buffered. Pitch 72 halves.
// LAYOUT: 0 flat [M,N] fp32 out; 1 [B,H,S,Dk] fp16; 2 [B,H,Dk,S] fp16 (V^T).
// ---------------------------------------------------------------------------
#define HP 72
#define GST (128*HP)               // halves per stage per operand
#define GEMM_SMEM (4*GST*2)        // 73728 B

template<int LAYOUT>
__global__ __launch_bounds__(256)
void gemm_f16(const __half* __restrict__ X, const __half* __restrict__ W,
              const float* __restrict__ bias, void* __restrict__ Yv,
              float scale)
{
    extern __shared__ __half smh[];
    __half* A = smh;
    __half* B = smh + 2 * GST;
    const int m0 = blockIdx.y * 128, n0 = blockIdx.x * 128;
    const int tid = threadIdx.x, lane = tid & 31, warp = tid >> 5;
    const int g = lane >> 2, tg = lane & 3;
    const int wm = (warp & 3) * 32, wn = (warp >> 2) * 64;
    const uint32_t sA = (uint32_t)__cvta_generic_to_shared(A);
    const uint32_t sB = (uint32_t)__cvta_generic_to_shared(B);

    // stage = 128 rows x 64 halves (128B = 8 chunks); A then B: 2048 chunks
#define G_ISSUE(st, k0)                                                        \
    {                                                                          \
        _Pragma("unroll")                                                      \
        for (int i = 0; i < 8; i++) {                                          \
            int c = tid + i * 256;                                             \
            int r = (c >> 3) & 127, ch = c & 7;                                \
            if (c < 1024)                                                      \
                cp16(sA + ((st) * GST + r * HP) * 2 + ch * 16,                 \
                     X + (size_t)(m0 + r) * DMODEL + (k0) + ch * 8);           \
            else                                                               \
                cp16(sB + ((st) * GST + r * HP) * 2 + ch * 16,                 \
                     W + (size_t)(n0 + r) * DMODEL + (k0) + ch * 8);           \
        }                                                                      \
    }

    G_ISSUE(0, 0);  cpcommit();
    G_ISSUE(1, 64); cpcommit();

    float acc[2][8][4];
#pragma unroll
    for (int t = 0; t < 2; t++)
#pragma unroll
        for (int j = 0; j < 8; j++)
#pragma unroll
            for (int c = 0; c < 4; c++) acc[t][j][c] = 0.f;

    for (int kt = 0; kt < 8; kt++) {
        cpwait<1>();
        __syncthreads();
        const __half* As = A + (kt & 1) * GST;
        const __half* Bs = B + (kt & 1) * GST;
#pragma unroll
        for (int kc = 0; kc < 4; kc++) {
            const int k = kc * 16;
            uint32_t a[2][4];
#pragma unroll
            for (int t = 0; t < 2; t++) {
                const int r = wm + t * 16;
                a[t][0] = LD32(&As[(r + g    ) * HP + k + 2 * tg]);
                a[t][1] = LD32(&As[(r + g + 8) * HP + k + 2 * tg]);
                a[t][2] = LD32(&As[(r + g    ) * HP + k + 8 + 2 * tg]);
                a[t][3] = LD32(&As[(r + g + 8) * HP + k + 8 + 2 * tg]);
            }
#pragma unroll
            for (int j = 0; j < 8; j++) {
                uint32_t b0 = LD32(&Bs[(wn + j * 8 + g) * HP + k + 2 * tg]);
                uint32_t b1 = LD32(&Bs[(wn + j * 8 + g) * HP + k + 8 + 2 * tg]);
                mma_f16(acc[0][j], a[0], b0, b1);
                mma_f16(acc[1][j], a[1], b0, b1);
            }
        }
        __syncthreads();
        if (kt + 2 < 8) { G_ISSUE(kt & 1, (kt + 2) * 64); }
        cpcommit();
    }

#pragma unroll
    for (int t = 0; t < 2; t++) {
#pragma unroll
        for (int rr = 0; rr < 2; rr++) {
            const int r = m0 + wm + t * 16 + g + rr * 8;
            const int bb = r >> 12, ss = r & 4095;
#pragma unroll
            for (int j = 0; j < 8; j++) {
                const int n = n0 + wn + j * 8 + 2 * tg;
                float2 bi = *(const float2*)&bias[n];
                float v0 = (acc[t][j][rr * 2 + 0] + bi.x) * scale;
                float v1 = (acc[t][j][rr * 2 + 1] + bi.y) * scale;
                if (LAYOUT == 0) {
                    *(float2*)&((float*)Yv)[(size_t)r * DMODEL + n]
                        = make_float2(v0, v1);
                } else if (LAYOUT == 1) {
                    const int h = n >> 6, d = n & 63;
                    *(__half2*)&((__half*)Yv)[
                        (((size_t)(bb * NHEAD + h)) * SEQ + ss) * DK + d]
                        = __floats2half2_rn(v0, v1);
                } else {
                    const int h = n >> 6, d = n & 63;
                    __half* yb = (__half*)Yv
                        + (((size_t)(bb * NHEAD + h)) * DK + d) * SEQ + ss;
                    yb[0]   = __float2half_rn(v0);
                    yb[SEQ] = __float2half_rn(v1);
                }
            }
        }
    }
#undef G_ISSUE
}

// ---------------------------------------------------------------------------
// fp16 flash attention: 256 thr (8 warps) x 256 query rows, 32 rows/warp
// (2 m16 halves, K/V B-fragments amortized 2x). m16n8k16 fp16 MMA, fp32 acc.
// K/V 64-key tiles double-buffered via cp.async; V transposed in gmem.
// Softmax in exp2 domain (log2e folded into Q projection scale).
// ---------------------------------------------------------------------------
#define QROWS 256
#define KVB (64*HP)                       // halves per K or V stage
#define SM_K (QROWS*HP)                   // P/Q buffer first
#define SM_V (SM_K + 2*KVB)
#define ATT_SMEM ((SM_V + 2*KVB)*2)       // 73728 B

__global__ __launch_bounds__(256)
void attn_kernel()
{
    extern __shared__ __half smh[];
    __half* Pb = smh;                // [256][HP]  Q then P (warp-private rows)

    const int bh = blockIdx.y, q0 = blockIdx.x * QROWS;
    const int tid = threadIdx.x, lane = tid & 31, warp = tid >> 5;
    const int g = lane >> 2, tg = lane & 3;
    const int w32 = warp * 32;

    const __half* Qg = g_qh + (size_t)bh * SEQ * DK + (size_t)q0 * DK;
    const __half* Kg = g_kh + (size_t)bh * SEQ * DK;
    const __half* Vg = g_vh + (size_t)bh * DK * SEQ;

    const uint32_t sP = (uint32_t)__cvta_generic_to_shared(smh);
    const uint32_t sK = sP + SM_K * 2;
    const uint32_t sV = sP + SM_V * 2;

    // Q tile: 256 rows x 8 chunks = 2048
#pragma unroll
    for (int i = 0; i < 8; i++) {
        int c = tid + i * 256;
        int row = c >> 3, ch = c & 7;
        cp16(sP + row * (HP * 2) + ch * 16, Qg + (size_t)row * DK + ch * 8);
    }
    cpcommit();

    // K,V tiles: 64 rows x 8 chunks each = 1024
#define KV_ISSUE(st, ktile)                                                    \
    {                                                                          \
        _Pragma("unroll")                                                      \
        for (int i = 0; i < 4; i++) {                                          \
            int c = tid + i * 256;                                             \
            int r = (c >> 3) & 63, ch = c & 7;                                 \
            if (c < 512)                                                       \
                cp16(sK + (st) * (KVB * 2) + r * (HP * 2) + ch * 16,           \
                     Kg + ((size_t)(ktile) * 64 + r) * DK + ch * 8);           \
            else                                                               \
                cp16(sV + (st) * (KVB * 2) + r * (HP * 2) + ch * 16,           \
                     Vg + (size_t)r * SEQ + (ktile) * 64 + ch * 8);            \
        }                                                                      \
    }

    KV_ISSUE(0, 0); cpcommit();
    KV_ISSUE(1, 1); cpcommit();

    cpwait<2>();
    __syncthreads();

    // Q fragments in registers: 2 m16 halves x 4 k16 chunks x 4 regs
    uint32_t qa[2][4][4];
#pragma unroll
    for (int h = 0; h < 2; h++) {
        const int mr = w32 + h * 16;
#pragma unroll
        for (int kc = 0; kc < 4; kc++) {
            const int k = kc * 16;
            qa[h][kc][0] = LD32(&Pb[(mr + g    ) * HP + k + 2 * tg]);
            qa[h][kc][1] = LD32(&Pb[(mr + g + 8) * HP + k + 2 * tg]);
            qa[h][kc][2] = LD32(&Pb[(mr + g    ) * HP + k + 8 + 2 * tg]);
            qa[h][kc][3] = LD32(&Pb[(mr + g + 8) * HP + k + 8 + 2 * tg]);
        }
    }

    float o[2][8][4];
    float m[2][2], l[2][2];
#pragma unroll
    for (int h = 0; h < 2; h++) {
        m[h][0] = -1e30f; m[h][1] = -1e30f; l[h][0] = 0.f; l[h][1] = 0.f;
#pragma unroll
        for (int nt = 0; nt < 8; nt++)
#pragma unroll
            for (int c = 0; c < 4; c++) o[h][nt][c] = 0.f;
    }

    for (int kt = 0; kt < SEQ / 64; kt++) {
        cpwait<1>();
        __syncthreads();
        const __half* Ks = smh + SM_K + (kt & 1) * KVB;
        const __half* Vs = smh + SM_V + (kt & 1) * KVB;

        // S = Q @ K^T (K fragments shared across both halves)
        float sc[2][8][4];
#pragma unroll
        for (int h = 0; h < 2; h++)
#pragma unroll
            for (int nt = 0; nt < 8; nt++)
#pragma unroll
                for (int c = 0; c < 4; c++) sc[h][nt][c] = 0.f;

#pragma unroll
        for (int nt = 0; nt < 8; nt++) {
            const int rk = (nt * 8 + g) * HP;
#pragma unroll
            for (int kc = 0; kc < 4; kc++) {
                const int k = kc * 16;
                uint32_t b0 = LD32(&Ks[rk + k + 2 * tg]);
                uint32_t b1 = LD32(&Ks[rk + k + 8 + 2 * tg]);
                mma_f16(sc[0][nt], qa[0][kc], b0, b1);
                mma_f16(sc[1][nt], qa[1][kc], b0, b1);
            }
        }

        // Online softmax (exp2 domain) per half
#pragma unroll
        for (int h = 0; h < 2; h++) {
            float mx0 = -1e30f, mx1 = -1e30f;
#pragma unroll
            for (int nt = 0; nt < 8; nt++) {
                mx0 = fmaxf(mx0, fmaxf(sc[h][nt][0], sc[h][nt][1]));
                mx1 = fmaxf(mx1, fmaxf(sc[h][nt][2], sc[h][nt][3]));
            }
            mx0 = fmaxf(mx0, __shfl_xor_sync(0xffffffffu, mx0, 1));
            mx0 = fmaxf(mx0, __shfl_xor_sync(0xffffffffu, mx0, 2));
            mx1 = fmaxf(mx1, __shfl_xor_sync(0xffffffffu, mx1, 1));
            mx1 = fmaxf(mx1, __shfl_xor_sync(0xffffffffu, mx1, 2));

            const float mn0 = fmaxf(m[h][0], mx0), mn1 = fmaxf(m[h][1], mx1);
            const float c0 = ex2(m[h][0] - mn0), c1 = ex2(m[h][1] - mn1);
            m[h][0] = mn0; m[h][1] = mn1;

            float s0 = 0.f, s1 = 0.f;
            const int rA = w32 + h * 16 + g;
#pragma unroll
            for (int nt = 0; nt < 8; nt++) {
                float p00 = ex2(sc[h][nt][0] - mn0);
                float p01 = ex2(sc[h][nt][1] - mn0);
                float p10 = ex2(sc[h][nt][2] - mn1);
                float p11 = ex2(sc[h][nt][3] - mn1);
                s0 += p00 + p01;
                s1 += p10 + p11;
                *(__half2*)&Pb[(rA    ) * HP + nt * 8 + 2 * tg]
                    = __floats2half2_rn(p00, p01);
                *(__half2*)&Pb[(rA + 8) * HP + nt * 8 + 2 * tg]
                    = __floats2half2_rn(p10, p11);
            }
            s0 += __shfl_xor_sync(0xffffffffu, s0, 1);
            s0 += __shfl_xor_sync(0xffffffffu, s0, 2);
            s1 += __shfl_xor_sync(0xffffffffu, s1, 1);
            s1 += __shfl_xor_sync(0xffffffffu, s1, 2);
            l[h][0] = l[h][0] * c0 + s0;
            l[h][1] = l[h][1] * c1 + s1;
#pragma unroll
            for (int nt = 0; nt < 8; nt++) {
                o[h][nt][0] *= c0; o[h][nt][1] *= c0;
                o[h][nt][2] *= c1; o[h][nt][3] *= c1;
            }
        }
        __syncwarp();   // P rows are warp-private

        // O += P @ V (V fragments shared across halves)
#pragma unroll
        for (int kc = 0; kc < 4; kc++) {
            const int k = kc * 16;
            uint32_t pa[2][4];
#pragma unroll
            for (int h = 0; h < 2; h++) {
                const int mr = w32 + h * 16;
                pa[h][0] = LD32(&Pb[(mr + g    ) * HP + k + 2 * tg]);
                pa[h][1] = LD32(&Pb[(mr + g + 8) * HP + k + 2 * tg]);
                pa[h][2] = LD32(&Pb[(mr + g    ) * HP + k + 8 + 2 * tg]);
                pa[h][3] = LD32(&Pb[(mr + g + 8) * HP + k + 8 + 2 * tg]);
            }
#pragma unroll
            for (int nt = 0; nt < 8; nt++) {
                const int rv = (nt * 8 + g) * HP;
                uint32_t b0 = LD32(&Vs[rv + k + 2 * tg]);
                uint32_t b1 = LD32(&Vs[rv + k + 8 + 2 * tg]);
                mma_f16(o[0][nt], pa[0], b0, b1);
                mma_f16(o[1][nt], pa[1], b0, b1);
            }
        }
        __syncthreads();   // all warps done with stage before refill
        if (kt + 2 < SEQ / 64) { KV_ISSUE(kt & 1, kt + 2); }
        cpcommit();
    }

    // Epilogue: normalize, write fp16 [B,S,D] (feeds fp16 O-GEMM)
    const int bb = bh >> 3, hh = bh & 7;
    __half* Og = g_att + ((size_t)bb * SEQ + q0) * DMODEL + hh * DK;
#pragma unroll
    for (int h = 0; h < 2; h++) {
#pragma unroll
        for (int rr = 0; rr < 2; rr++) {
            const float inv = 1.0f / l[h][rr];
            const int row = w32 + h * 16 + g + rr * 8;
#pragma unroll
            for (int nt = 0; nt < 8; nt++) {
                *(__half2*)&Og[(size_t)row * DMODEL + nt * 8 + 2 * tg]
                    = __floats2half2_rn(o[h][nt][rr * 2 + 0] * inv,
                                        o[h][nt][rr * 2 + 1] * inv);
            }
        }
    }
#undef KV_ISSUE
}

// ---------------------------------------------------------------------------
extern "C" void kernel_launch(void* const* d_in, const int* in_sizes, int n_in,
                              void* d_out, int out_size)
{
    const float* q  = (const float*)d_in[0];
    const float* k  = (const float*)d_in[1];
    const float* v  = (const float*)d_in[2];
    const float* wq = (const float*)d_in[3];
    const float* bq = (const float*)d_in[4];
    const float* wk = (const float*)d_in[5];
    const float* bk = (const float*)d_in[6];
    const float* wv = (const float*)d_in[7];
    const float* bv = (const float*)d_in[8];
    const float* wo = (const float*)d_in[9];
    const float* bo = (const float*)d_in[10];

    __half *qh, *kh, *vh, *att, *rq, *rk, *rv, *rw;
    cudaGetSymbolAddress((void**)&qh,  g_qh);
    cudaGetSymbolAddress((void**)&kh,  g_kh);
    cudaGetSymbolAddress((void**)&vh,  g_vh);
    cudaGetSymbolAddress((void**)&att, g_att);
    cudaGetSymbolAddress((void**)&rq,  g_rq);
    cudaGetSymbolAddress((void**)&rk,  g_rk);
    cudaGetSymbolAddress((void**)&rv,  g_rv);
    cudaGetSymbolAddress((void**)&rw,  g_rw);

    cudaFuncSetAttribute(gemm_f16<0>,
        cudaFuncAttributeMaxDynamicSharedMemorySize, GEMM_SMEM);
    cudaFuncSetAttribute(gemm_f16<1>,
        cudaFuncAttributeMaxDynamicSharedMemorySize, GEMM_SMEM);
    cudaFuncSetAttribute(gemm_f16<2>,
        cudaFuncAttributeMaxDynamicSharedMemorySize, GEMM_SMEM);
    cudaFuncSetAttribute(attn_kernel,
        cudaFuncAttributeMaxDynamicSharedMemorySize, ATT_SMEM);

    const int DD = DMODEL * DMODEL;
    const int n4x = MTOT * DMODEL / 4;   // 1048576
    const int n4w = DD / 4;              // 65536

    conv3_kernel<<<dim3(256, 3), 256>>>((const float4*)q, (const float4*)k,
                                        (const float4*)v, (__half2*)rq,
                                        (__half2*)rk, (__half2*)rv, n4x);
    conv4_kernel<<<dim3(128, 4), 256>>>((const float4*)wq, (const float4*)wk,
                                        (const float4*)wv, (const float4*)wo,
                                        (__half2*)rw, n4w);

    dim3 gg(DMODEL / 128, MTOT / 128);   // (4, 64)
    const float QSCALE = 0.125f * 1.4426950408889634f;   // 1/sqrt(Dk) * log2e
    gemm_f16<1><<<gg, 256, GEMM_SMEM>>>(rq, rw + 0 * DD, bq, qh, QSCALE);
    gemm_f16<1><<<gg, 256, GEMM_SMEM>>>(rk, rw + 1 * DD, bk, kh, 1.0f);
    gemm_f16<2><<<gg, 256, GEMM_SMEM>>>(rv, rw + 2 * DD, bv, vh, 1.0f);

    attn_kernel<<<dim3(SEQ / QROWS, BATCH * NHEAD), 256, ATT_SMEM>>>();

    gemm_f16<0><<<gg, 256, GEMM_SMEM>>>(att, rw + 3 * DD, bo, d_out, 1.0f);
}

// round 9
// speedup vs baseline: 2.4936x; 1.1343x over previous
#include <cuda_runtime.h>
#include <cuda_fp16.h>
#include <cstdint>

#define DMODEL 512
#define NHEAD  8
#define DK     64
#define BATCH  2
#define SEQ    4096
#define MTOT   (BATCH*SEQ)   // 8192

// Scratch (static device arrays — no runtime allocation). All fp16.
__device__ __half g_qh[(size_t)BATCH*NHEAD*SEQ*DK];   // [B,H,S,Dk], *(log2e/8)
__device__ __half g_kh[(size_t)BATCH*NHEAD*SEQ*DK];   // [B,H,S,Dk]
__device__ __half g_vh[(size_t)BATCH*NHEAD*SEQ*DK];   // [B,H,Dk,S] TRANSPOSED
__device__ __half g_att[(size_t)MTOT*DMODEL];         // [B,S,D]
__device__ __half g_rq[(size_t)MTOT*DMODEL];          // fp16 inputs
__device__ __half g_rk[(size_t)MTOT*DMODEL];
__device__ __half g_rv[(size_t)MTOT*DMODEL];
__device__ __half g_rw[(size_t)4*DMODEL*DMODEL];      // fp16 weights

// ---------------------------------------------------------------------------
__device__ __forceinline__ float ex2(float x) {
    float r;
    asm("ex2.approx.ftz.f32 %0, %1;" : "=f"(r) : "f"(x));
    return r;
}

__device__ __forceinline__ void mma_f16(float* d, const uint32_t* a,
                                        uint32_t b0, uint32_t b1) {
    asm volatile(
        "mma.sync.aligned.m16n8k16.row.col.f32.f16.f16.f32 "
        "{%0,%1,%2,%3}, {%4,%5,%6,%7}, {%8,%9}, {%0,%1,%2,%3};\n"
        : "+f"(d[0]), "+f"(d[1]), "+f"(d[2]), "+f"(d[3])
        : "r"(a[0]), "r"(a[1]), "r"(a[2]), "r"(a[3]), "r"(b0), "r"(b1));
}

__device__ __forceinline__ void ldsm4(uint32_t& r0, uint32_t& r1,
                                      uint32_t& r2, uint32_t& r3,
                                      uint32_t saddr) {
    asm volatile(
        "ldmatrix.sync.aligned.m8n8.x4.shared.b16 {%0,%1,%2,%3}, [%4];"
        : "=r"(r0), "=r"(r1), "=r"(r2), "=r"(r3) : "r"(saddr));
}

__device__ __forceinline__ uint32_t h2(float lo, float hi) {
    __half2 v = __floats2half2_rn(lo, hi);
    return *(uint32_t*)&v;
}

__device__ __forceinline__ void cp16(uint32_t saddr, const void* g) {
    asm volatile("cp.async.cg.shared.global [%0], [%1], 16;\n"
                 :: "r"(saddr), "l"(g));
}
__device__ __forceinline__ void cpcommit() {
    asm volatile("cp.async.commit_group;\n");
}
template<int N> __device__ __forceinline__ void cpwait() {
    asm volatile("cp.async.wait_group %0;\n" :: "n"(N));
}

// ---------------------------------------------------------------------------
// Batched f32 -> f16 conversion (rn)
// ---------------------------------------------------------------------------
__global__ void conv3_kernel(const float4* __restrict__ s0,
                             const float4* __restrict__ s1,
                             const float4* __restrict__ s2,
                             __half2* __restrict__ d0,
                             __half2* __restrict__ d1,
                             __half2* __restrict__ d2, int n4)
{
    const float4* s = (blockIdx.y == 0) ? s0 : (blockIdx.y == 1) ? s1 : s2;
    __half2*      d = (blockIdx.y == 0) ? d0 : (blockIdx.y == 1) ? d1 : d2;
    for (int i = blockIdx.x * blockDim.x + threadIdx.x; i < n4;
         i += gridDim.x * blockDim.x) {
        float4 v = s[i];
        d[i * 2 + 0] = __floats2half2_rn(v.x, v.y);
        d[i * 2 + 1] = __floats2half2_rn(v.z, v.w);
    }
}

__global__ void conv4_kernel(const float4* __restrict__ s0,
                             const float4* __restrict__ s1,
                             const float4* __restrict__ s2,
                             const float4* __restrict__ s3,
                             __half2* __restrict__ dst, int n4)
{
    const float4* s = (blockIdx.y == 0) ? s0 : (blockIdx.y == 1) ? s1
                    : (blockIdx.y == 2) ? s2 : s3;
    __half2* d = dst + (size_t)blockIdx.y * n4 * 2;
    for (int i = blockIdx.x * blockDim.x + threadIdx.x; i < n4;
         i += gridDim.x * blockDim.x) {
        float4 v = s[i];
        d[i * 2 + 0] = __floats2half2_rn(v.x, v.y);
        d[i * 2 + 1] = __floats2half2_rn(v.z, v.w);
    }
}

// ---------------------------------------------------------------------------
// fp16 GEMM core: 128x128 output tile, k64 stages (8), 256 thr (8 warps
// 4Mx2N), cp.async double-buffered, ldmatrix.x4 fragment loads.
// LAYOUT: 0 flat [M,N] fp32 out; 1 [B,H,S,Dk] fp16; 2 [B,H,Dk,S] fp16 (V^T).
// ---------------------------------------------------------------------------
#define HP 72
#define GST (128*HP)               // halves per stage per operand
#define GEMM_SMEM (4*GST*2)        // 73728 B

template<int LAYOUT>
__device__ __forceinline__
void gemm_body(const __half* __restrict__ X, const __half* __restrict__ W,
               const float* __restrict__ bias, void* __restrict__ Yv,
               float scale, int m0, int n0, __half* smh)
{
    __half* A = smh;
    const int tid = threadIdx.x, lane = tid & 31, warp = tid >> 5;
    const int g = lane >> 2, tg = lane & 3;
    const int wm = (warp & 3) * 32, wn = (warp >> 2) * 64;
    const uint32_t sA = (uint32_t)__cvta_generic_to_shared(A);
    const uint32_t sB = sA + 2 * GST * 2;
    // ldmatrix lane-address components
    const int lj  = lane >> 3, lr = lane & 7;
    const int rA8 = (lj & 1) * 8, kA8 = (lj >> 1) * 8;   // A-frag pattern
    const int rB8 = (lj >> 1) * 8, kB8 = (lj & 1) * 8;   // B-frag pattern

#define G_ISSUE(st, k0)                                                        \
    {                                                                          \
        _Pragma("unroll")                                                      \
        for (int i = 0; i < 8; i++) {                                          \
            int c = tid + i * 256;                                             \
            int r = (c >> 3) & 127, ch = c & 7;                                \
            if (c < 1024)                                                      \
                cp16(sA + ((st) * GST + r * HP) * 2 + ch * 16,                 \
                     X + (size_t)(m0 + r) * DMODEL + (k0) + ch * 8);           \
            else                                                               \
                cp16(sB + ((st) * GST + r * HP) * 2 + ch * 16,                 \
                     W + (size_t)(n0 + r) * DMODEL + (k0) + ch * 8);           \
        }                                                                      \
    }

    G_ISSUE(0, 0);  cpcommit();
    G_ISSUE(1, 64); cpcommit();

    float acc[2][8][4];
#pragma unroll
    for (int t = 0; t < 2; t++)
#pragma unroll
        for (int j = 0; j < 8; j++)
#pragma unroll
            for (int c = 0; c < 4; c++) acc[t][j][c] = 0.f;

    for (int kt = 0; kt < 8; kt++) {
        cpwait<1>();
        __syncthreads();
        const uint32_t Ab = sA + (kt & 1) * GST * 2;
        const uint32_t Bb = sB + (kt & 1) * GST * 2;
#pragma unroll
        for (int kc = 0; kc < 4; kc++) {
            uint32_t a[2][4];
#pragma unroll
            for (int t = 0; t < 2; t++) {
                const int row = wm + t * 16 + rA8 + lr;
                const int ko  = kc * 16 + kA8;
                ldsm4(a[t][0], a[t][1], a[t][2], a[t][3],
                      Ab + (row * HP + ko) * 2);
            }
#pragma unroll
            for (int jp = 0; jp < 4; jp++) {
                uint32_t b[4];
                const int row = wn + jp * 16 + rB8 + lr;
                const int ko  = kc * 16 + kB8;
                ldsm4(b[0], b[1], b[2], b[3], Bb + (row * HP + ko) * 2);
                mma_f16(acc[0][2 * jp    ], a[0], b[0], b[1]);
                mma_f16(acc[1][2 * jp    ], a[1], b[0], b[1]);
                mma_f16(acc[0][2 * jp + 1], a[0], b[2], b[3]);
                mma_f16(acc[1][2 * jp + 1], a[1], b[2], b[3]);
            }
        }
        __syncthreads();
        if (kt + 2 < 8) { G_ISSUE(kt & 1, (kt + 2) * 64); }
        cpcommit();
    }

#pragma unroll
    for (int t = 0; t < 2; t++) {
#pragma unroll
        for (int rr = 0; rr < 2; rr++) {
            const int r = m0 + wm + t * 16 + g + rr * 8;
            const int bb = r >> 12, ss = r & 4095;
#pragma unroll
            for (int j = 0; j < 8; j++) {
                const int n = n0 + wn + j * 8 + 2 * tg;
                float2 bi = *(const float2*)&bias[n];
                float v0 = (acc[t][j][rr * 2 + 0] + bi.x) * scale;
                float v1 = (acc[t][j][rr * 2 + 1] + bi.y) * scale;
                if (LAYOUT == 0) {
                    *(float2*)&((float*)Yv)[(size_t)r * DMODEL + n]
                        = make_float2(v0, v1);
                } else if (LAYOUT == 1) {
                    const int h = n >> 6, d = n & 63;
                    *(__half2*)&((__half*)Yv)[
                        (((size_t)(bb * NHEAD + h)) * SEQ + ss) * DK + d]
                        = __floats2half2_rn(v0, v1);
                } else {
                    const int h = n >> 6, d = n & 63;
                    __half* yb = (__half*)Yv
                        + (((size_t)(bb * NHEAD + h)) * DK + d) * SEQ + ss;
                    yb[0]   = __float2half_rn(v0);
                    yb[SEQ] = __float2half_rn(v1);
                }
            }
        }
    }
#undef G_ISSUE
}

// Fused QKV projections: blockIdx.z selects input/weight/output.
__global__ __launch_bounds__(256)
void gemm_qkv(const __half* __restrict__ rq, const __half* __restrict__ rk,
              const __half* __restrict__ rv, const __half* __restrict__ rw,
              const float* __restrict__ bq, const float* __restrict__ bk,
              const float* __restrict__ bv,
              __half* __restrict__ qh, __half* __restrict__ kh,
              __half* __restrict__ vh, float qscale)
{
    extern __shared__ __half smh[];
    const int m0 = blockIdx.y * 128, n0 = blockIdx.x * 128;
    const int DD = DMODEL * DMODEL;
    if (blockIdx.z == 0)
        gemm_body<1>(rq, rw,          bq, qh, qscale, m0, n0, smh);
    else if (blockIdx.z == 1)
        gemm_body<1>(rk, rw + DD,     bk, kh, 1.0f,   m0, n0, smh);
    else
        gemm_body<2>(rv, rw + 2 * DD, bv, vh, 1.0f,   m0, n0, smh);
}

// Output projection (fp32 result into d_out)
__global__ __launch_bounds__(256)
void gemm_o(const __half* __restrict__ X, const __half* __restrict__ W,
            const float* __restrict__ bias, float* __restrict__ Y)
{
    extern __shared__ __half smh[];
    gemm_body<0>(X, W, bias, Y, 1.0f, blockIdx.y * 128, blockIdx.x * 128, smh);
}

// ---------------------------------------------------------------------------
// fp16 flash attention: 256 thr (8 warps) x 256 query rows, 32 rows/warp
// (2 m16 halves, K/V fragments shared). P stays ENTIRELY in registers
// (S C-fragment == PV A-fragment for fp16). ldmatrix.x4 for Q/K/V frags.
// Softmax in exp2 domain (log2e folded into Q projection scale).
// ---------------------------------------------------------------------------
#define QROWS 256
#define KVB (64*HP)                       // halves per K or V stage
#define SM_K (QROWS*HP)                   // Q buffer first
#define SM_V (SM_K + 2*KVB)
#define ATT_SMEM ((SM_V + 2*KVB)*2)       // 73728 B

__global__ __launch_bounds__(256)
void attn_kernel()
{
    extern __shared__ __half smh[];

    const int bh = blockIdx.y, q0 = blockIdx.x * QROWS;
    const int tid = threadIdx.x, lane = tid & 31, warp = tid >> 5;
    const int w32 = warp * 32;
    const int lj = lane >> 3, lr = lane & 7;
    const int rA8 = (lj & 1) * 8, kA8 = (lj >> 1) * 8;   // A-frag addr pattern
    const int rB8 = (lj >> 1) * 8, kB8 = (lj & 1) * 8;   // B-frag addr pattern

    const __half* Qg = g_qh + (size_t)bh * SEQ * DK + (size_t)q0 * DK;
    const __half* Kg = g_kh + (size_t)bh * SEQ * DK;
    const __half* Vg = g_vh + (size_t)bh * DK * SEQ;

    const uint32_t sQ = (uint32_t)__cvta_generic_to_shared(smh);
    const uint32_t sK = sQ + SM_K * 2;
    const uint32_t sV = sQ + SM_V * 2;

    // Q tile: 256 rows x 8 chunks = 2048
#pragma unroll
    for (int i = 0; i < 8; i++) {
        int c = tid + i * 256;
        int row = c >> 3, ch = c & 7;
        cp16(sQ + row * (HP * 2) + ch * 16, Qg + (size_t)row * DK + ch * 8);
    }
    cpcommit();

#define KV_ISSUE(st, ktile)                                                    \
    {                                                                          \
        _Pragma("unroll")                                                      \
        for (int i = 0; i < 4; i++) {                                          \
            int c = tid + i * 256;                                             \
            int r = (c >> 3) & 63, ch = c & 7;                                 \
            if (c < 512)                                                       \
                cp16(sK + (st) * (KVB * 2) + r * (HP * 2) + ch * 16,           \
                     Kg + ((size_t)(ktile) * 64 + r) * DK + ch * 8);           \
            else                                                               \
                cp16(sV + (st) * (KVB * 2) + r * (HP * 2) + ch * 16,           \
                     Vg + (size_t)r * SEQ + (ktile) * 64 + ch * 8);            \
        }                                                                      \
    }

    KV_ISSUE(0, 0); cpcommit();
    KV_ISSUE(1, 1); cpcommit();

    cpwait<2>();
    __syncthreads();

    // Q fragments via ldmatrix: 2 halves x 4 k16 chunks
    uint32_t qa[2][4][4];
#pragma unroll
    for (int h = 0; h < 2; h++)
#pragma unroll
        for (int kc = 0; kc < 4; kc++) {
            const int row = w32 + h * 16 + rA8 + lr;
            const int ko  = kc * 16 + kA8;
            ldsm4(qa[h][kc][0], qa[h][kc][1], qa[h][kc][2], qa[h][kc][3],
                  sQ + (row * HP + ko) * 2);
        }

    float o[2][8][4];
    float m[2][2], l[2][2];
#pragma unroll
    for (int h = 0; h < 2; h++) {
        m[h][0] = -1e30f; m[h][1] = -1e30f; l[h][0] = 0.f; l[h][1] = 0.f;
#pragma unroll
        for (int nt = 0; nt < 8; nt++)
#pragma unroll
            for (int c = 0; c < 4; c++) o[h][nt][c] = 0.f;
    }

    for (int kt = 0; kt < SEQ / 64; kt++) {
        cpwait<1>();
        __syncthreads();
        const uint32_t kbase = sK + (kt & 1) * (KVB * 2);
        const uint32_t vbase = sV + (kt & 1) * (KVB * 2);

        // ---- S = Q @ K^T ----
        float sc[2][8][4];
#pragma unroll
        for (int h = 0; h < 2; h++)
#pragma unroll
            for (int nt = 0; nt < 8; nt++)
#pragma unroll
                for (int c = 0; c < 4; c++) sc[h][nt][c] = 0.f;

#pragma unroll
        for (int kc = 0; kc < 4; kc++) {
            uint32_t kb[4][4];
#pragma unroll
            for (int np = 0; np < 4; np++) {
                const int key = np * 16 + rB8 + lr;
                const int ko  = kc * 16 + kB8;
                ldsm4(kb[np][0], kb[np][1], kb[np][2], kb[np][3],
                      kbase + (key * HP + ko) * 2);
            }
#pragma unroll
            for (int np = 0; np < 4; np++) {
                mma_f16(sc[0][2 * np    ], qa[0][kc], kb[np][0], kb[np][1]);
                mma_f16(sc[1][2 * np    ], qa[1][kc], kb[np][0], kb[np][1]);
                mma_f16(sc[0][2 * np + 1], qa[0][kc], kb[np][2], kb[np][3]);
                mma_f16(sc[1][2 * np + 1], qa[1][kc], kb[np][2], kb[np][3]);
            }
        }

        // ---- Online softmax (exp2 domain); p overwrites sc ----
#pragma unroll
        for (int h = 0; h < 2; h++) {
            float mx0 = -1e30f, mx1 = -1e30f;
#pragma unroll
            for (int nt = 0; nt < 8; nt++) {
                mx0 = fmaxf(mx0, fmaxf(sc[h][nt][0], sc[h][nt][1]));
                mx1 = fmaxf(mx1, fmaxf(sc[h][nt][2], sc[h][nt][3]));
            }
            mx0 = fmaxf(mx0, __shfl_xor_sync(0xffffffffu, mx0, 1));
            mx0 = fmaxf(mx0, __shfl_xor_sync(0xffffffffu, mx0, 2));
            mx1 = fmaxf(mx1, __shfl_xor_sync(0xffffffffu, mx1, 1));
            mx1 = fmaxf(mx1, __shfl_xor_sync(0xffffffffu, mx1, 2));

            const float mn0 = fmaxf(m[h][0], mx0), mn1 = fmaxf(m[h][1], mx1);
            const float c0 = ex2(m[h][0] - mn0), c1 = ex2(m[h][1] - mn1);
            m[h][0] = mn0; m[h][1] = mn1;

            float s0 = 0.f, s1 = 0.f;
#pragma unroll
            for (int nt = 0; nt < 8; nt++) {
                sc[h][nt][0] = ex2(sc[h][nt][0] - mn0);
                sc[h][nt][1] = ex2(sc[h][nt][1] - mn0);
                sc[h][nt][2] = ex2(sc[h][nt][2] - mn1);
                sc[h][nt][3] = ex2(sc[h][nt][3] - mn1);
                s0 += sc[h][nt][0] + sc[h][nt][1];
                s1 += sc[h][nt][2] + sc[h][nt][3];
            }
            s0 += __shfl_xor_sync(0xffffffffu, s0, 1);
            s0 += __shfl_xor_sync(0xffffffffu, s0, 2);
            s1 += __shfl_xor_sync(0xffffffffu, s1, 1);
            s1 += __shfl_xor_sync(0xffffffffu, s1, 2);
            l[h][0] = l[h][0] * c0 + s0;
            l[h][1] = l[h][1] * c1 + s1;
#pragma unroll
            for (int nt = 0; nt < 8; nt++) {
                o[h][nt][0] *= c0; o[h][nt][1] *= c0;
                o[h][nt][2] *= c1; o[h][nt][3] *= c1;
            }
        }

        // ---- O += P @ V : P packed in registers (C-frag == A-frag) ----
#pragma unroll
        for (int kc = 0; kc < 4; kc++) {
            uint32_t vb[4][4];
#pragma unroll
            for (int np = 0; np < 4; np++) {
                const int d  = np * 16 + rB8 + lr;
                const int ko = kc * 16 + kB8;
                ldsm4(vb[np][0], vb[np][1], vb[np][2], vb[np][3],
                      vbase + (d * HP + ko) * 2);
            }
            const int n0b = 2 * kc, n1b = 2 * kc + 1;
            uint32_t pa0[4], pa1[4];
            pa0[0] = h2(sc[0][n0b][0], sc[0][n0b][1]);
            pa0[1] = h2(sc[0][n0b][2], sc[0][n0b][3]);
            pa0[2] = h2(sc[0][n1b][0], sc[0][n1b][1]);
            pa0[3] = h2(sc[0][n1b][2], sc[0][n1b][3]);
            pa1[0] = h2(sc[1][n0b][0], sc[1][n0b][1]);
            pa1[1] = h2(sc[1][n0b][2], sc[1][n0b][3]);
            pa1[2] = h2(sc[1][n1b][0], sc[1][n1b][1]);
            pa1[3] = h2(sc[1][n1b][2], sc[1][n1b][3]);
#pragma unroll
            for (int np = 0; np < 4; np++) {
                mma_f16(o[0][2 * np    ], pa0, vb[np][0], vb[np][1]);
                mma_f16(o[1][2 * np    ], pa1, vb[np][0], vb[np][1]);
                mma_f16(o[0][2 * np + 1], pa0, vb[np][2], vb[np][3]);
                mma_f16(o[1][2 * np + 1], pa1, vb[np][2], vb[np][3]);
            }
        }
        __syncthreads();   // all warps done with stage before refill
        if (kt + 2 < SEQ / 64) { KV_ISSUE(kt & 1, kt + 2); }
        cpcommit();
    }

    // Epilogue: normalize, write fp16 [B,S,D] (feeds fp16 O-GEMM)
    const int g = lane >> 2, tg = lane & 3;
    const int bb = bh >> 3, hh = bh & 7;
    __half* Og = g_att + ((size_t)bb * SEQ + q0) * DMODEL + hh * DK;
#pragma unroll
    for (int h = 0; h < 2; h++) {
#pragma unroll
        for (int rr = 0; rr < 2; rr++) {
            const float inv = 1.0f / l[h][rr];
            const int row = w32 + h * 16 + g + rr * 8;
#pragma unroll
            for (int nt = 0; nt < 8; nt++) {
                *(__half2*)&Og[(size_t)row * DMODEL + nt * 8 + 2 * tg]
                    = __floats2half2_rn(o[h][nt][rr * 2 + 0] * inv,
                                        o[h][nt][rr * 2 + 1] * inv);
            }
        }
    }
#undef KV_ISSUE
}

// ---------------------------------------------------------------------------
extern "C" void kernel_launch(void* const* d_in, const int* in_sizes, int n_in,
                              void* d_out, int out_size)
{
    const float* q  = (const float*)d_in[0];
    const float* k  = (const float*)d_in[1];
    const float* v  = (const float*)d_in[2];
    const float* wq = (const float*)d_in[3];
    const float* bq = (const float*)d_in[4];
    const float* wk = (const float*)d_in[5];
    const float* bk = (const float*)d_in[6];
    const float* wv = (const float*)d_in[7];
    const float* bv = (const float*)d_in[8];
    const float* wo = (const float*)d_in[9];
    const float* bo = (const float*)d_in[10];

    __half *qh, *kh, *vh, *att, *rq, *rk, *rv, *rw;
    cudaGetSymbolAddress((void**)&qh,  g_qh);
    cudaGetSymbolAddress((void**)&kh,  g_kh);
    cudaGetSymbolAddress((void**)&vh,  g_vh);
    cudaGetSymbolAddress((void**)&att, g_att);
    cudaGetSymbolAddress((void**)&rq,  g_rq);
    cudaGetSymbolAddress((void**)&rk,  g_rk);
    cudaGetSymbolAddress((void**)&rv,  g_rv);
    cudaGetSymbolAddress((void**)&rw,  g_rw);

    cudaFuncSetAttribute(gemm_qkv,
        cudaFuncAttributeMaxDynamicSharedMemorySize, GEMM_SMEM);
    cudaFuncSetAttribute(gemm_o,
        cudaFuncAttributeMaxDynamicSharedMemorySize, GEMM_SMEM);
    cudaFuncSetAttribute(attn_kernel,
        cudaFuncAttributeMaxDynamicSharedMemorySize, ATT_SMEM);

    const int DD = DMODEL * DMODEL;
    const int n4x = MTOT * DMODEL / 4;   // 1048576
    const int n4w = DD / 4;              // 65536

    conv3_kernel<<<dim3(256, 3), 256>>>((const float4*)q, (const float4*)k,
                                        (const float4*)v, (__half2*)rq,
                                        (__half2*)rk, (__half2*)rv, n4x);
    conv4_kernel<<<dim3(128, 4), 256>>>((const float4*)wq, (const float4*)wk,
                                        (const float4*)wv, (const float4*)wo,
                                        (__half2*)rw, n4w);

    const float QSCALE = 0.125f * 1.4426950408889634f;   // 1/sqrt(Dk) * log2e
    gemm_qkv<<<dim3(DMODEL / 128, MTOT / 128, 3), 256, GEMM_SMEM>>>(
        rq, rk, rv, rw, bq, bk, bv, qh, kh, vh, QSCALE);

    attn_kernel<<<dim3(SEQ / QROWS, BATCH * NHEAD), 256, ATT_SMEM>>>();

    gemm_o<<<dim3(DMODEL / 128, MTOT / 128), 256, GEMM_SMEM>>>(
        att, rw + 3 * DD, bo, (float*)d_out);
}